// round 5
// baseline (speedup 1.0000x reference)
#include <cuda_runtime.h>
#include <math.h>

#define N_NODES   100000
#define N_EDGES   1600000
#define IN_FEAT   128
#define N_HEADS   8
#define OUT_FEAT  16
#define HF        128
#define NEG_SLOPE 0.2f

#define SCAN_B    512
#define NB1       ((N_NODES + SCAN_B - 1) / SCAN_B)   // 196

// ---------------- device scratch ----------------
__device__ float d_h   [N_NODES * HF];
__device__ float d_q   [N_NODES * N_HEADS];
__device__ float d_kk  [N_NODES * N_HEADS];
__device__ int   d_deg [N_NODES];
__device__ int   d_off [N_NODES];
__device__ int   d_pos [N_NODES];
__device__ int   d_csrc[N_EDGES];
__device__ int   d_bsum[NB1];
__device__ int   d_bsum2[NB1];

// ---------------- K0: init ----------------
__global__ void k_init() {
    int i = blockIdx.x * blockDim.x + threadIdx.x;
    if (i < N_NODES) d_deg[i] = 0;
}

// ---------------- K1: tiled GEMM  h = x@Wv+bv  (+ fused q/k epilogue) ----
#define BM 64
#define BK 16
__global__ __launch_bounds__(256) void k_gemm(const float* __restrict__ x,
                                              const float* __restrict__ Wv,
                                              const float* __restrict__ bv,
                                              const float* __restrict__ Wq,
                                              const float* __restrict__ bq,
                                              const float* __restrict__ Wk,
                                              const float* __restrict__ bk) {
    __shared__ float Xs[BK][BM + 1];       // ~4.2 KB
    __shared__ float Ws[BK * HF];          // 8 KB (reused for Wq|Wk in epilogue)
    __shared__ float Hs[BM][HF + 4];       // 33.8 KB, stride 132 (16B aligned, cf-free)

    const int tid = threadIdx.x;
    const int tx  = tid & 31;
    const int ty  = tid >> 5;
    const int bm  = blockIdx.x * BM;

    float acc[8][4];
#pragma unroll
    for (int m = 0; m < 8; ++m)
#pragma unroll
        for (int j = 0; j < 4; ++j) acc[m][j] = 0.0f;

    for (int k0 = 0; k0 < IN_FEAT; k0 += BK) {
#pragma unroll
        for (int i = 0; i < 4; ++i) {
            int idx = tid + i * 256;
            int nl  = idx >> 4;
            int kk  = idx & 15;
            int node = bm + nl;
            Xs[kk][nl] = (node < N_NODES) ? x[(size_t)node * IN_FEAT + k0 + kk] : 0.0f;
        }
#pragma unroll
        for (int i = 0; i < 8; ++i) {
            int idx = tid + i * 256;
            int kk  = idx >> 7;
            int f   = idx & 127;
            Ws[kk * HF + f] = Wv[(size_t)(k0 + kk) * HF + f];
        }
        __syncthreads();

#pragma unroll
        for (int kk = 0; kk < BK; ++kk) {
            float4 w = *(const float4*)&Ws[kk * HF + tx * 4];
            float xm[8];
#pragma unroll
            for (int m = 0; m < 8; ++m) xm[m] = Xs[kk][ty * 8 + m];
#pragma unroll
            for (int m = 0; m < 8; ++m) {
                acc[m][0] = fmaf(xm[m], w.x, acc[m][0]);
                acc[m][1] = fmaf(xm[m], w.y, acc[m][1]);
                acc[m][2] = fmaf(xm[m], w.z, acc[m][2]);
                acc[m][3] = fmaf(xm[m], w.w, acc[m][3]);
            }
        }
        __syncthreads();
    }

    // epilogue: bias, write h to gmem + smem
    float4 bias = *(const float4*)&bv[tx * 4];
#pragma unroll
    for (int m = 0; m < 8; ++m) {
        int nl = ty * 8 + m;
        int node = bm + nl;
        float4 r;
        r.x = acc[m][0] + bias.x;
        r.y = acc[m][1] + bias.y;
        r.z = acc[m][2] + bias.z;
        r.w = acc[m][3] + bias.w;
        *(float4*)&Hs[nl][tx * 4] = r;
        if (node < N_NODES)
            *(float4*)&d_h[(size_t)node * HF + tx * 4] = r;
    }

    // load Wq (1024) | Wk (1024) into Ws
#pragma unroll
    for (int i = 0; i < 4; ++i) {
        int idx = tid + i * 256;
        Ws[idx]        = Wq[idx];
        Ws[idx + 1024] = Wk[idx];
    }
    __syncthreads();

    // fused q/k: 4 threads per node, each does heads {2p, 2p+1} for q and k
    {
        const int nl = tid >> 2;            // 0..63
        const int p  = tid & 3;
        const int h0 = 2 * p, h1 = 2 * p + 1;
        float qa0 = 0.f, qa1 = 0.f, ka0 = 0.f, ka1 = 0.f;
#pragma unroll
        for (int j = 0; j < HF; j += 4) {
            float4 hv = *(const float4*)&Hs[nl][j];
#pragma unroll
            for (int jj = 0; jj < 4; ++jj) {
                float hx = (&hv.x)[jj];
                int base = (j + jj) * N_HEADS;
                qa0 = fmaf(hx, Ws[base + h0], qa0);
                qa1 = fmaf(hx, Ws[base + h1], qa1);
                ka0 = fmaf(hx, Ws[1024 + base + h0], ka0);
                ka1 = fmaf(hx, Ws[1024 + base + h1], ka1);
            }
        }
        const int node = bm + nl;
        if (node < N_NODES) {
            d_q [node * N_HEADS + h0] = qa0 + bq[h0];
            d_q [node * N_HEADS + h1] = qa1 + bq[h1];
            d_kk[node * N_HEADS + h0] = ka0 + bk[h0];
            d_kk[node * N_HEADS + h1] = ka1 + bk[h1];
        }
    }
}

// ---------------- CSR build (vectorized) ----------------
__global__ void k_count(const int* __restrict__ dst) {
    int i = blockIdx.x * blockDim.x + threadIdx.x;
    if (i >= N_EDGES / 4) return;
    int4 d = ((const int4*)dst)[i];
    atomicAdd(&d_deg[d.x], 1);
    atomicAdd(&d_deg[d.y], 1);
    atomicAdd(&d_deg[d.z], 1);
    atomicAdd(&d_deg[d.w], 1);
}

__global__ __launch_bounds__(SCAN_B) void k_scan1() {
    __shared__ int tmp[2][SCAN_B];
    const int t = threadIdx.x;
    const int i = blockIdx.x * SCAN_B + t;
    int v = (i < N_NODES) ? d_deg[i] : 0;
    tmp[0][t] = v;
    __syncthreads();
    int pp = 0;
    for (int off = 1; off < SCAN_B; off <<= 1) {
        int xv = tmp[pp][t];
        if (t >= off) xv += tmp[pp][t - off];
        tmp[pp ^ 1][t] = xv;
        pp ^= 1;
        __syncthreads();
    }
    int incl = tmp[pp][t];
    if (i < N_NODES) d_off[i] = incl - v;
    if (t == SCAN_B - 1) d_bsum[blockIdx.x] = incl;
}

__global__ __launch_bounds__(256) void k_scan2() {
    __shared__ int tmp[2][256];
    const int t = threadIdx.x;
    int v = (t < NB1) ? d_bsum[t] : 0;
    tmp[0][t] = v;
    __syncthreads();
    int pp = 0;
    for (int off = 1; off < 256; off <<= 1) {
        int xv = tmp[pp][t];
        if (t >= off) xv += tmp[pp][t - off];
        tmp[pp ^ 1][t] = xv;
        pp ^= 1;
        __syncthreads();
    }
    if (t < NB1) d_bsum2[t] = tmp[pp][t] - v;
}

__global__ __launch_bounds__(SCAN_B) void k_scan3() {
    const int i = blockIdx.x * SCAN_B + threadIdx.x;
    if (i < N_NODES) {
        int o = d_off[i] + d_bsum2[blockIdx.x];
        d_off[i] = o;
        d_pos[i] = o;
    }
}

__global__ void k_fill(const int* __restrict__ src, const int* __restrict__ dst) {
    int i = blockIdx.x * blockDim.x + threadIdx.x;
    if (i >= N_EDGES / 4) return;
    int4 d = ((const int4*)dst)[i];
    int4 s = ((const int4*)src)[i];
    d_csrc[atomicAdd(&d_pos[d.x], 1)] = s.x;
    d_csrc[atomicAdd(&d_pos[d.y], 1)] = s.y;
    d_csrc[atomicAdd(&d_pos[d.z], 1)] = s.z;
    d_csrc[atomicAdd(&d_pos[d.w], 1)] = s.w;
}

// ---------------- K3: fused softmax + aggregate + normalize + head-mean ----
// one warp per dst node; lane l covers feats [4l,4l+4), head = l>>2
__global__ __launch_bounds__(128) void k_agg(float* __restrict__ out) {
    const int n = blockIdx.x * 4 + (threadIdx.x >> 5);
    if (n >= N_NODES) return;
    const int l  = threadIdx.x & 31;
    const int hd = l >> 2;

    const float qv    = d_q[n * N_HEADS + hd];
    const int   start = d_off[n];
    const int   deg   = d_deg[n];

    float4 acc = make_float4(0.f, 0.f, 0.f, 0.f);
    float  den = 0.f;

    int j = 0;
    for (; j + 3 < deg; j += 4) {
        const int s0 = d_csrc[start + j];
        const int s1 = d_csrc[start + j + 1];
        const int s2 = d_csrc[start + j + 2];
        const int s3 = d_csrc[start + j + 3];
        const float kk0 = d_kk[s0 * N_HEADS + hd];
        const float kk1 = d_kk[s1 * N_HEADS + hd];
        const float kk2 = d_kk[s2 * N_HEADS + hd];
        const float kk3 = d_kk[s3 * N_HEADS + hd];
        const float4 h0 = *(const float4*)&d_h[(size_t)s0 * HF + l * 4];
        const float4 h1 = *(const float4*)&d_h[(size_t)s1 * HF + l * 4];
        const float4 h2 = *(const float4*)&d_h[(size_t)s2 * HF + l * 4];
        const float4 h3 = *(const float4*)&d_h[(size_t)s3 * HF + l * 4];
        float c0 = kk0 + qv; c0 = (c0 >= 0.f) ? c0 : NEG_SLOPE * c0;
        float c1 = kk1 + qv; c1 = (c1 >= 0.f) ? c1 : NEG_SLOPE * c1;
        float c2 = kk2 + qv; c2 = (c2 >= 0.f) ? c2 : NEG_SLOPE * c2;
        float c3 = kk3 + qv; c3 = (c3 >= 0.f) ? c3 : NEG_SLOPE * c3;
        const float e0 = __expf(c0);
        const float e1 = __expf(c1);
        const float e2 = __expf(c2);
        const float e3 = __expf(c3);
        acc.x = fmaf(e0, h0.x, acc.x); acc.y = fmaf(e0, h0.y, acc.y);
        acc.z = fmaf(e0, h0.z, acc.z); acc.w = fmaf(e0, h0.w, acc.w);
        acc.x = fmaf(e1, h1.x, acc.x); acc.y = fmaf(e1, h1.y, acc.y);
        acc.z = fmaf(e1, h1.z, acc.z); acc.w = fmaf(e1, h1.w, acc.w);
        acc.x = fmaf(e2, h2.x, acc.x); acc.y = fmaf(e2, h2.y, acc.y);
        acc.z = fmaf(e2, h2.z, acc.z); acc.w = fmaf(e2, h2.w, acc.w);
        acc.x = fmaf(e3, h3.x, acc.x); acc.y = fmaf(e3, h3.y, acc.y);
        acc.z = fmaf(e3, h3.z, acc.z); acc.w = fmaf(e3, h3.w, acc.w);
        den += (e0 + e1) + (e2 + e3);
    }
    for (; j < deg; ++j) {
        const int s0 = d_csrc[start + j];
        const float kk0 = d_kk[s0 * N_HEADS + hd];
        const float4 h0 = *(const float4*)&d_h[(size_t)s0 * HF + l * 4];
        float c0 = kk0 + qv; c0 = (c0 >= 0.f) ? c0 : NEG_SLOPE * c0;
        const float e0 = __expf(c0);
        acc.x = fmaf(e0, h0.x, acc.x); acc.y = fmaf(e0, h0.y, acc.y);
        acc.z = fmaf(e0, h0.z, acc.z); acc.w = fmaf(e0, h0.w, acc.w);
        den += e0;
    }

    const float inv = (deg > 0) ? 1.0f / den : 0.0f;
    acc.x *= inv; acc.y *= inv; acc.z *= inv; acc.w *= inv;

#pragma unroll
    for (int off = 4; off < 32; off <<= 1) {
        acc.x += __shfl_xor_sync(0xffffffff, acc.x, off);
        acc.y += __shfl_xor_sync(0xffffffff, acc.y, off);
        acc.z += __shfl_xor_sync(0xffffffff, acc.z, off);
        acc.w += __shfl_xor_sync(0xffffffff, acc.w, off);
    }

    if (l < 4) {
        float4 r;
        r.x = acc.x * (1.0f / N_HEADS);
        r.y = acc.y * (1.0f / N_HEADS);
        r.z = acc.z * (1.0f / N_HEADS);
        r.w = acc.w * (1.0f / N_HEADS);
        *(float4*)&out[(size_t)n * OUT_FEAT + l * 4] = r;
    }
}

// ---------------- launch ----------------
extern "C" void kernel_launch(void* const* d_in, const int* in_sizes, int n_in,
                              void* d_out, int out_size) {
    const float* x   = (const float*)d_in[0];
    const int*   src = (const int*)d_in[1];
    const int*   dst = (const int*)d_in[2];
    const float* Wv  = (const float*)d_in[3];
    const float* bv  = (const float*)d_in[4];
    const float* Wq  = (const float*)d_in[5];
    const float* bq  = (const float*)d_in[6];
    const float* Wk  = (const float*)d_in[7];
    const float* bk  = (const float*)d_in[8];
    float* out = (float*)d_out;

    k_init <<<(N_NODES + 255) / 256, 256>>>();
    k_gemm <<<(N_NODES + BM - 1) / BM, 256>>>(x, Wv, bv, Wq, bq, Wk, bk);
    k_count<<<(N_EDGES / 4 + 255) / 256, 256>>>(dst);
    k_scan1<<<NB1, SCAN_B>>>();
    k_scan2<<<1, 256>>>();
    k_scan3<<<NB1, SCAN_B>>>();
    k_fill <<<(N_EDGES / 4 + 255) / 256, 256>>>(src, dst);
    k_agg  <<<(N_NODES + 3) / 4, 128>>>(out);
}

// round 6
// speedup vs baseline: 1.1752x; 1.1752x over previous
#include <cuda_runtime.h>
#include <cuda_fp16.h>
#include <math.h>

#define N_NODES   100000
#define N_EDGES   1600000
#define IN_FEAT   128
#define N_HEADS   8
#define OUT_FEAT  16
#define HF        128
#define NEG_SLOPE 0.2f

#define SCAN_B    512
#define NB1       ((N_NODES + SCAN_B - 1) / SCAN_B)   // 196

// ---------------- device scratch ----------------
__device__ float  d_h   [N_NODES * HF];       // fp32 h (for q/k projection)
__device__ __half d_h16 [N_NODES * HF];       // fp16 h (for edge gather)
__device__ float  d_q   [N_NODES * N_HEADS];
__device__ float  d_kk  [N_NODES * N_HEADS];
__device__ int    d_deg [N_NODES];
__device__ int    d_off [N_NODES];
__device__ int    d_pos [N_NODES];
__device__ int    d_csrc[N_EDGES];
__device__ int    d_bsum[NB1];
__device__ int    d_bsum2[NB1];

// ---------------- K0: init ----------------
__global__ void k_init() {
    int i = blockIdx.x * blockDim.x + threadIdx.x;
    if (i < N_NODES) d_deg[i] = 0;
}

// ---------------- K1: tiled GEMM  h = x @ Wv + bv ----------------
#define BM 64
#define BK 16
__global__ __launch_bounds__(256) void k_gemm(const float* __restrict__ x,
                                              const float* __restrict__ Wv,
                                              const float* __restrict__ bv) {
    __shared__ float Xs[BK][BM + 1];
    __shared__ float Ws[BK][HF];

    const int tid = threadIdx.x;
    const int tx  = tid & 31;
    const int ty  = tid >> 5;
    const int bm  = blockIdx.x * BM;

    float acc[8][4];
#pragma unroll
    for (int m = 0; m < 8; ++m)
#pragma unroll
        for (int j = 0; j < 4; ++j) acc[m][j] = 0.0f;

    for (int k0 = 0; k0 < IN_FEAT; k0 += BK) {
#pragma unroll
        for (int i = 0; i < 4; ++i) {
            int idx = tid + i * 256;
            int nl  = idx >> 4;
            int kk  = idx & 15;
            int node = bm + nl;
            Xs[kk][nl] = (node < N_NODES) ? x[(size_t)node * IN_FEAT + k0 + kk] : 0.0f;
        }
#pragma unroll
        for (int i = 0; i < 8; ++i) {
            int idx = tid + i * 256;
            int kk  = idx >> 7;
            int f   = idx & 127;
            Ws[kk][f] = Wv[(size_t)(k0 + kk) * HF + f];
        }
        __syncthreads();

#pragma unroll
        for (int kk = 0; kk < BK; ++kk) {
            float4 w = *(const float4*)&Ws[kk][tx * 4];
            float xm[8];
#pragma unroll
            for (int m = 0; m < 8; ++m) xm[m] = Xs[kk][ty * 8 + m];
#pragma unroll
            for (int m = 0; m < 8; ++m) {
                acc[m][0] = fmaf(xm[m], w.x, acc[m][0]);
                acc[m][1] = fmaf(xm[m], w.y, acc[m][1]);
                acc[m][2] = fmaf(xm[m], w.z, acc[m][2]);
                acc[m][3] = fmaf(xm[m], w.w, acc[m][3]);
            }
        }
        __syncthreads();
    }

    float4 bias = *(const float4*)&bv[tx * 4];
#pragma unroll
    for (int m = 0; m < 8; ++m) {
        int node = bm + ty * 8 + m;
        if (node < N_NODES) {
            float4 r;
            r.x = acc[m][0] + bias.x;
            r.y = acc[m][1] + bias.y;
            r.z = acc[m][2] + bias.z;
            r.w = acc[m][3] + bias.w;
            *(float4*)&d_h[(size_t)node * HF + tx * 4] = r;
            // fp16 copy for the edge gather
            uint2 p;
            __half2 p0 = __floats2half2_rn(r.x, r.y);
            __half2 p1 = __floats2half2_rn(r.z, r.w);
            p.x = *reinterpret_cast<unsigned int*>(&p0);
            p.y = *reinterpret_cast<unsigned int*>(&p1);
            *(uint2*)&d_h16[(size_t)node * HF + tx * 4] = p;
        }
    }
}

// ---------------- K2: q/k projections ----------------
__global__ __launch_bounds__(128) void k_qk(const float* __restrict__ Wq,
                                            const float* __restrict__ bq,
                                            const float* __restrict__ Wk,
                                            const float* __restrict__ bk) {
    __shared__ float hs[8][HF];
    __shared__ float Wqs[HF * N_HEADS];
    __shared__ float Wks[HF * N_HEADS];

    const int t = threadIdx.x;
    const int nb = blockIdx.x * 8;

#pragma unroll
    for (int i = 0; i < 8; ++i) {
        int idx = t + i * 128;
        Wqs[idx] = Wq[idx];
        Wks[idx] = Wk[idx];
    }
#pragma unroll
    for (int i = 0; i < 8; ++i) {
        int idx = t + i * 128;
        int nl = idx >> 7;
        int j  = idx & 127;
        int node = nb + nl;
        hs[nl][j] = (node < N_NODES) ? d_h[(size_t)node * HF + j] : 0.0f;
    }
    __syncthreads();

    const int nl  = t >> 4;
    const int id  = t & 15;
    const int hd  = id & 7;
    const bool isQ = (id < 8);
    const int node = nb + nl;
    if (node >= N_NODES) return;

    const float* W = isQ ? Wqs : Wks;
    float s = isQ ? bq[hd] : bk[hd];
#pragma unroll 16
    for (int j = 0; j < HF; ++j)
        s = fmaf(hs[nl][j], W[j * N_HEADS + hd], s);

    if (isQ) d_q [node * N_HEADS + hd] = s;
    else     d_kk[node * N_HEADS + hd] = s;
}

// ---------------- CSR build ----------------
__global__ void k_count(const int* __restrict__ dst) {
    int i = blockIdx.x * blockDim.x + threadIdx.x;
    if (i >= N_EDGES / 4) return;
    int4 d = ((const int4*)dst)[i];
    atomicAdd(&d_deg[d.x], 1);
    atomicAdd(&d_deg[d.y], 1);
    atomicAdd(&d_deg[d.z], 1);
    atomicAdd(&d_deg[d.w], 1);
}

__global__ __launch_bounds__(SCAN_B) void k_scan1() {
    __shared__ int tmp[2][SCAN_B];
    const int t = threadIdx.x;
    const int i = blockIdx.x * SCAN_B + t;
    int v = (i < N_NODES) ? d_deg[i] : 0;
    tmp[0][t] = v;
    __syncthreads();
    int pp = 0;
    for (int off = 1; off < SCAN_B; off <<= 1) {
        int xv = tmp[pp][t];
        if (t >= off) xv += tmp[pp][t - off];
        tmp[pp ^ 1][t] = xv;
        pp ^= 1;
        __syncthreads();
    }
    int incl = tmp[pp][t];
    if (i < N_NODES) d_off[i] = incl - v;
    if (t == SCAN_B - 1) d_bsum[blockIdx.x] = incl;
}

__global__ __launch_bounds__(256) void k_scan2() {
    __shared__ int tmp[2][256];
    const int t = threadIdx.x;
    int v = (t < NB1) ? d_bsum[t] : 0;
    tmp[0][t] = v;
    __syncthreads();
    int pp = 0;
    for (int off = 1; off < 256; off <<= 1) {
        int xv = tmp[pp][t];
        if (t >= off) xv += tmp[pp][t - off];
        tmp[pp ^ 1][t] = xv;
        pp ^= 1;
        __syncthreads();
    }
    if (t < NB1) d_bsum2[t] = tmp[pp][t] - v;
}

__global__ __launch_bounds__(SCAN_B) void k_scan3() {
    const int i = blockIdx.x * SCAN_B + threadIdx.x;
    if (i < N_NODES) {
        int o = d_off[i] + d_bsum2[blockIdx.x];
        d_off[i] = o;
        d_pos[i] = o;
    }
}

__global__ void k_fill(const int* __restrict__ src, const int* __restrict__ dst) {
    int i = blockIdx.x * blockDim.x + threadIdx.x;
    if (i >= N_EDGES / 4) return;
    int4 d = ((const int4*)dst)[i];
    int4 s = ((const int4*)src)[i];
    d_csrc[atomicAdd(&d_pos[d.x], 1)] = s.x;
    d_csrc[atomicAdd(&d_pos[d.y], 1)] = s.y;
    d_csrc[atomicAdd(&d_pos[d.z], 1)] = s.z;
    d_csrc[atomicAdd(&d_pos[d.w], 1)] = s.w;
}

// ---------------- K3: fused softmax + aggregate + normalize + head-mean ----
// one warp per dst node; lane l covers feats [4l,4l+4), head = l>>2
// h gathered in fp16 (uint2 = 8B per lane)
__device__ __forceinline__ void agg_edge(int s, int hd, int l, float qv,
                                         float4& acc, float& den) {
    const float kk = d_kk[s * N_HEADS + hd];
    const uint2 u  = *(const uint2*)&d_h16[(size_t)s * HF + l * 4];
    float c = kk + qv; c = (c >= 0.f) ? c : NEG_SLOPE * c;
    const float e = __expf(c);
    const __half2 p0 = *reinterpret_cast<const __half2*>(&u.x);
    const __half2 p1 = *reinterpret_cast<const __half2*>(&u.y);
    const float2 f0 = __half22float2(p0);
    const float2 f1 = __half22float2(p1);
    acc.x = fmaf(e, f0.x, acc.x); acc.y = fmaf(e, f0.y, acc.y);
    acc.z = fmaf(e, f1.x, acc.z); acc.w = fmaf(e, f1.y, acc.w);
    den += e;
}

__global__ __launch_bounds__(128) void k_agg(float* __restrict__ out) {
    const int n = blockIdx.x * 4 + (threadIdx.x >> 5);
    if (n >= N_NODES) return;
    const int l  = threadIdx.x & 31;
    const int hd = l >> 2;

    const float qv    = d_q[n * N_HEADS + hd];
    const int   start = d_off[n];
    const int   deg   = d_deg[n];

    float4 acc = make_float4(0.f, 0.f, 0.f, 0.f);
    float  den = 0.f;

    int j = 0;
    for (; j + 3 < deg; j += 4) {
        const int s0 = d_csrc[start + j];
        const int s1 = d_csrc[start + j + 1];
        const int s2 = d_csrc[start + j + 2];
        const int s3 = d_csrc[start + j + 3];
        agg_edge(s0, hd, l, qv, acc, den);
        agg_edge(s1, hd, l, qv, acc, den);
        agg_edge(s2, hd, l, qv, acc, den);
        agg_edge(s3, hd, l, qv, acc, den);
    }
    for (; j < deg; ++j)
        agg_edge(d_csrc[start + j], hd, l, qv, acc, den);

    const float inv = (deg > 0) ? 1.0f / den : 0.0f;
    acc.x *= inv; acc.y *= inv; acc.z *= inv; acc.w *= inv;

#pragma unroll
    for (int off = 4; off < 32; off <<= 1) {
        acc.x += __shfl_xor_sync(0xffffffff, acc.x, off);
        acc.y += __shfl_xor_sync(0xffffffff, acc.y, off);
        acc.z += __shfl_xor_sync(0xffffffff, acc.z, off);
        acc.w += __shfl_xor_sync(0xffffffff, acc.w, off);
    }

    if (l < 4) {
        float4 r;
        r.x = acc.x * (1.0f / N_HEADS);
        r.y = acc.y * (1.0f / N_HEADS);
        r.z = acc.z * (1.0f / N_HEADS);
        r.w = acc.w * (1.0f / N_HEADS);
        *(float4*)&out[(size_t)n * OUT_FEAT + l * 4] = r;
    }
}

// ---------------- launch ----------------
extern "C" void kernel_launch(void* const* d_in, const int* in_sizes, int n_in,
                              void* d_out, int out_size) {
    const float* x   = (const float*)d_in[0];
    const int*   src = (const int*)d_in[1];
    const int*   dst = (const int*)d_in[2];
    const float* Wv  = (const float*)d_in[3];
    const float* bv  = (const float*)d_in[4];
    const float* Wq  = (const float*)d_in[5];
    const float* bq  = (const float*)d_in[6];
    const float* Wk  = (const float*)d_in[7];
    const float* bk  = (const float*)d_in[8];
    float* out = (float*)d_out;

    k_init <<<(N_NODES + 255) / 256, 256>>>();
    k_gemm <<<(N_NODES + BM - 1) / BM, 256>>>(x, Wv, bv);
    k_qk   <<<(N_NODES + 7) / 8, 128>>>(Wq, bq, Wk, bk);
    k_count<<<(N_EDGES / 4 + 255) / 256, 256>>>(dst);
    k_scan1<<<NB1, SCAN_B>>>();
    k_scan2<<<1, 256>>>();
    k_scan3<<<NB1, SCAN_B>>>();
    k_fill <<<(N_EDGES / 4 + 255) / 256, 256>>>(src, dst);
    k_agg  <<<(N_NODES + 3) / 4, 128>>>(out);
}